// round 17
// baseline (speedup 1.0000x reference)
#include <cuda_runtime.h>
#include <cuda_fp16.h>
#include <math.h>
#include <stdint.h>

// ---------------- dims ----------------
#define NPTS 131072
#define PTS  128            // points per block
#define TPB  128            // 4 warps, each owns 32 points (two m16 halves)
#define NBLK (NPTS/PTS)     // 1024
#define HID  128
#define L1_KT 13            // K = 208 (194 real + bias row + pad)
#define L23_KT 8            // K = 128

// ---------------- A smem layout (bytes) ----------------
#define SA_STRIDE 432       // feature row stride: 216 fp16 (16B-aligned)
#define SM_B2 0             // b2: 128 f32
#define SM_B3 512           // b3: 128 f32
#define SM_A  1024
#define SM_TOTAL (SM_A + 128*SA_STRIDE)   // 56320 -> 3 blocks/SM at <=170 regs

// weight fragment array (uint4 units): [layer][kt][ntpair 0..7][lane]
#define WF_L1 0
#define WF_L2 3328          // 13*256
#define WF_L3 5376          // + 8*256
#define WF_TOTAL4 7424      // + 8*256 = 29 * 256 exactly

// prologue grid split
#define PRO_TRANS 1024
#define PRO_FRAG  29
#define PRO_TOTAL (PRO_TRANS + PRO_FRAG + 1)

// ---------------- device scratch ----------------
__device__ uint32_t g_zt16[16*64*64*32];     // z transposed (B,H,W,C/2) packed half2
__device__ uint4 g_wfrag4[WF_TOTAL4];        // paired MMA b-fragments
__device__ uint4 g_hfrag[8*32];              // head b-fragments {b0h,b1h,b0l,b1l}
__device__ float g_hb[8];                    // head biases

// ---------------- helpers ----------------
__device__ __forceinline__ uint32_t smem_u32(const void* p) {
    uint32_t a;
    asm("{ .reg .u64 t; cvta.to.shared.u64 t, %1; cvt.u32.u64 %0, t; }" : "=r"(a) : "l"(p));
    return a;
}
__device__ __forceinline__ void ldsm4(uint32_t* r, uint32_t a) {
    asm volatile("ldmatrix.sync.aligned.m8n8.x4.shared.b16 {%0,%1,%2,%3}, [%4];"
                 : "=r"(r[0]), "=r"(r[1]), "=r"(r[2]), "=r"(r[3]) : "r"(a));
}
#define STS32(addr, v) asm volatile("st.shared.b32 [%0], %1;" :: "r"(addr), "r"(v) : "memory")
__device__ __forceinline__ void mma_f16(float* d, const uint32_t* a, uint32_t b0, uint32_t b1) {
    asm volatile("mma.sync.aligned.m16n8k16.row.col.f32.f16.f16.f32 "
                 "{%0,%1,%2,%3}, {%4,%5,%6,%7}, {%8,%9}, {%0,%1,%2,%3};"
                 : "+f"(d[0]), "+f"(d[1]), "+f"(d[2]), "+f"(d[3])
                 : "r"(a[0]), "r"(a[1]), "r"(a[2]), "r"(a[3]), "r"(b0), "r"(b1));
}
__device__ __forceinline__ void mma_f16_z(float* d, const uint32_t* a, uint32_t b0, uint32_t b1) {
    asm volatile("mma.sync.aligned.m16n8k16.row.col.f32.f16.f16.f32 "
                 "{%0,%1,%2,%3}, {%4,%5,%6,%7}, {%8,%9}, {%10,%10,%10,%10};"
                 : "=f"(d[0]), "=f"(d[1]), "=f"(d[2]), "=f"(d[3])
                 : "r"(a[0]), "r"(a[1]), "r"(a[2]), "r"(a[3]), "r"(b0), "r"(b1), "f"(0.f));
}
// hardware packed tanh: one MUFU op, two fp16 lanes
__device__ __forceinline__ uint32_t tanh_h2(uint32_t x) {
    uint32_t r;
    asm("tanh.approx.f16x2 %0, %1;" : "=r"(r) : "r"(x));
    return r;
}
// pack (a,b) -> fp16x2 word, low half = a
__device__ __forceinline__ uint32_t packh2(float a, float b) {
    __half2 h = __floats2half2_rn(a, b);
    return *reinterpret_cast<uint32_t*>(&h);
}
// pack (a,b) fp32 pair -> hi fp16x2 word + lo (residual) fp16x2 word
__device__ __forceinline__ void split2h(float a, float b, uint32_t& hi, uint32_t& lo) {
    __half ah = __float2half_rn(a), bh = __float2half_rn(b);
    __half al = __float2half_rn(a - __half2float(ah));
    __half bl = __float2half_rn(b - __half2float(bh));
    hi = (uint32_t)__half_as_ushort(ah) | ((uint32_t)__half_as_ushort(bh) << 16);
    lo = (uint32_t)__half_as_ushort(al) | ((uint32_t)__half_as_ushort(bl) << 16);
}
// fast sin/cos with explicit 2-step 2*pi range reduction
__device__ __forceinline__ void fsincos(float x, float& s, float& c) {
    float k = rintf(x * 0.15915494309189535f);
    float r = fmaf(-k, 6.2831855f, x);
    r = fmaf(-k, -1.7484555e-7f, r);
    s = __sinf(r);
    c = __cosf(r);
}
// head weight for output col n, input k
__device__ __forceinline__ float head_w(int k, int n,
    const float* Wvel, const float* Wfh, const float* Wph,
    const float* Wmu, const float* Wstd)
{
    if (n < 2) return Wvel[k * 2 + n];
    if (n < 4) return Wfh[k * 2 + n - 2];
    if (n < 6) return Wph[k * 2 + n - 4];
    if (n == 6) return Wmu[k];
    return Wstd[k];
}
// trunk weight for (layer, k, n)
__device__ __forceinline__ float trunk_w(int layer, int k, int n,
    const float* W1, const float* b1, const float* W2, const float* W3)
{
    if (layer == 1) {
        if (k < 194)  return W1[k * HID + n];
        if (k == 194) return b1[n];
        return 0.f;
    }
    const float* W = (layer == 2) ? W2 : W3;
    return W[k * HID + n];
}

// ---------------- fused prologue kernel ----------------
__global__ void __launch_bounds__(256) prologue_kernel(
    const float* __restrict__ z,
    const float* __restrict__ W1, const float* __restrict__ b1,
    const float* __restrict__ W2, const float* __restrict__ W3,
    const float* __restrict__ Wvel, const float* __restrict__ bvel,
    const float* __restrict__ Wfh,  const float* __restrict__ bfh,
    const float* __restrict__ Wph,  const float* __restrict__ bph,
    const float* __restrict__ Wmu,  const float* __restrict__ bmu,
    const float* __restrict__ Wstd, const float* __restrict__ bstd)
{
    __shared__ uint32_t tile[64][33];
    if (blockIdx.x < PRO_TRANS) {
        const int by = blockIdx.x;            // b*64 + y
        const int b = by >> 6, y = by & 63;
        const int tx = threadIdx.x & 63, ty = threadIdx.x >> 6;
        const float* src = z + ((b << 6) << 12) + (y << 6);
        #pragma unroll
        for (int j = 0; j < 8; j++) {
            int cp = j * 4 + ty;
            float v0 = __ldg(src + (2 * cp)     * 4096 + tx);
            float v1 = __ldg(src + (2 * cp + 1) * 4096 + tx);
            tile[tx][cp] = packh2(v0, v1);
        }
        __syncthreads();
        const int lane = threadIdx.x & 31, w = threadIdx.x >> 5;
        uint32_t* dst = g_zt16 + ((uint32_t)by << 11);
        #pragma unroll
        for (int j = 0; j < 8; j++) {
            int x = w * 8 + j;
            dst[(x << 5) + lane] = tile[x][lane];
        }
        return;
    }
    int pbid = blockIdx.x - PRO_TRANS;
    if (pbid < PRO_FRAG) {
        int i = pbid * 256 + threadIdx.x;
        int layer, rem;
        if (i < WF_L2)      { layer = 1; rem = i; }
        else if (i < WF_L3) { layer = 2; rem = i - WF_L2; }
        else                { layer = 3; rem = i - WF_L3; }
        int lane = rem & 31, np = (rem >> 5) & 7, kt = rem >> 8;
        int k0 = kt * 16 + (lane & 3) * 2;
        uint32_t w[4];
        #pragma unroll
        for (int h = 0; h < 2; h++) {
            int n = (2 * np + h) * 8 + (lane >> 2);
            float v[4];
            #pragma unroll
            for (int j = 0; j < 4; j++) {
                int k = k0 + (j >> 1) * 8 + (j & 1);
                v[j] = trunk_w(layer, k, n, W1, b1, W2, W3);
            }
            w[2 * h]     = packh2(v[0], v[1]);
            w[2 * h + 1] = packh2(v[2], v[3]);
        }
        g_wfrag4[i] = make_uint4(w[0], w[1], w[2], w[3]);
    } else {
        int t = threadIdx.x;
        int lane = t & 31, kt = t >> 5;
        int n  = lane >> 2;
        int k0 = kt * 16 + (lane & 3) * 2;
        float v[4];
        #pragma unroll
        for (int j = 0; j < 4; j++) {
            int k = k0 + (j >> 1) * 8 + (j & 1);
            v[j] = head_w(k, n, Wvel, Wfh, Wph, Wmu, Wstd);
        }
        uint4 o;
        split2h(v[0], v[1], o.x, o.z);
        split2h(v[2], v[3], o.y, o.w);
        g_hfrag[t] = o;
        if (t < 8) {
            float hb;
            if      (t < 2)  hb = bvel[t];
            else if (t < 4)  hb = bfh[t - 2];
            else if (t < 6)  hb = bph[t - 4];
            else if (t == 6) hb = bmu[0];
            else             hb = bstd[0];
            g_hb[t] = hb;
        }
    }
}

// 4 B-pairs (8 n-tiles) feeding BOTH m16 halves: each uint4 -> 4 MMAs
__device__ __forceinline__ void mma2_g4(float (*d)[16][4], const uint32_t* A0, const uint32_t* A1,
                                        const uint4* p, int npBase) {
    uint4 B[4];
    #pragma unroll
    for (int j = 0; j < 4; j++)
        B[j] = __ldg(p + (npBase + j) * 32);
    #pragma unroll
    for (int j = 0; j < 4; j++) {
        int nt = 2 * (npBase + j);
        mma_f16(d[0][nt],     A0, B[j].x, B[j].y);
        mma_f16(d[0][nt + 1], A0, B[j].z, B[j].w);
        mma_f16(d[1][nt],     A1, B[j].x, B[j].y);
        mma_f16(d[1][nt + 1], A1, B[j].z, B[j].w);
    }
}
__device__ __forceinline__ void mma2_g4_z(float (*d)[16][4], const uint32_t* A0, const uint32_t* A1,
                                          const uint4* p, int npBase) {
    uint4 B[4];
    #pragma unroll
    for (int j = 0; j < 4; j++)
        B[j] = __ldg(p + (npBase + j) * 32);
    #pragma unroll
    for (int j = 0; j < 4; j++) {
        int nt = 2 * (npBase + j);
        mma_f16_z(d[0][nt],     A0, B[j].x, B[j].y);
        mma_f16_z(d[0][nt + 1], A0, B[j].z, B[j].w);
        mma_f16_z(d[1][nt],     A1, B[j].x, B[j].y);
        mma_f16_z(d[1][nt + 1], A1, B[j].z, B[j].w);
    }
}

// ---------------- main kernel ----------------
__global__ void __launch_bounds__(TPB, 3) pinn_main(
    const float* __restrict__ coords, const float* __restrict__ fourierB,
    const float* __restrict__ b2g, const float* __restrict__ b3g,
    float* __restrict__ out)
{
    extern __shared__ __align__(16) unsigned char smem[];
    const uint32_t sb = smem_u32(smem);
    const int tid  = threadIdx.x;
    const int lane = tid & 31;
    const int warp = tid >> 5;        // 0..3, owns rows warp*32..warp*32+31

    float* sb2 = (float*)(smem + SM_B2);
    float* sb3 = (float*)(smem + SM_B3);
    sb2[tid] = b2g[tid];
    sb3[tid] = b3g[tid];

    // ================= warp-coalesced feature build (32 points per warp) ===========
    {
        const int m = blockIdx.x * PTS + warp * 32 + lane;   // one point per lane
        float cx = coords[m * 3 + 0];
        float cy = coords[m * 3 + 1];
        float ct = coords[m * 3 + 2];
        int bb_ = m >> 13;
        float fx = (cx + 1.f) * 0.5f * 63.f;
        float fy = (cy + 1.f) * 0.5f * 63.f;
        float x0f = floorf(fx), y0f = floorf(fy);
        int x0 = min(max((int)x0f, 0), 63);
        int x1 = max(min((int)x0f + 1, 63), 0);
        int y0 = min(max((int)y0f, 0), 63);
        int y1 = max(min((int)y0f + 1, 63), 0);
        float wa = (x0f + 1.f - fx) * (y0f + 1.f - fy);
        float wb = (x0f + 1.f - fx) * (fy - y0f);
        float wc = (fx - x0f) * (y0f + 1.f - fy);
        float wd = (fx - x0f) * (fy - y0f);
        int i00 = (((((bb_ << 6) + y0) << 6) + x0) << 5);
        int i01 = (((((bb_ << 6) + y1) << 6) + x0) << 5);
        int i10 = (((((bb_ << 6) + y0) << 6) + x1) << 5);
        int i11 = (((((bb_ << 6) + y1) << 6) + x1) << 5);

        const uint32_t* zt = g_zt16;
        const uint32_t rowBase = sb + SM_A + (uint32_t)(warp * 32) * SA_STRIDE;

        #pragma unroll 4
        for (int i = 0; i < 32; i++) {
            float wwa = __shfl_sync(0xffffffffu, wa, i);
            float wwb = __shfl_sync(0xffffffffu, wb, i);
            float wwc = __shfl_sync(0xffffffffu, wc, i);
            float wwd = __shfl_sync(0xffffffffu, wd, i);
            int a00 = __shfl_sync(0xffffffffu, i00, i);
            int a01 = __shfl_sync(0xffffffffu, i01, i);
            int a10 = __shfl_sync(0xffffffffu, i10, i);
            int a11 = __shfl_sync(0xffffffffu, i11, i);
            uint32_t wA = __ldg(zt + a00 + lane);
            uint32_t wB = __ldg(zt + a01 + lane);
            uint32_t wC = __ldg(zt + a10 + lane);
            uint32_t wD = __ldg(zt + a11 + lane);
            float2 A = __half22float2(*reinterpret_cast<__half2*>(&wA));
            float2 B = __half22float2(*reinterpret_cast<__half2*>(&wB));
            float2 C = __half22float2(*reinterpret_cast<__half2*>(&wC));
            float2 D = __half22float2(*reinterpret_cast<__half2*>(&wD));
            float v0 = wwa * A.x + wwb * B.x + wwc * C.x + wwd * D.x;
            float v1 = wwa * A.y + wwb * B.y + wwc * C.y + wwd * D.y;
            STS32(rowBase + i * SA_STRIDE + lane * 4, packh2(v0, v1));
        }

        float f0 = __ldg(fourierB + 2 * lane)     * 2.0943951023931953f;
        float f1 = __ldg(fourierB + 2 * lane + 1) * 2.0943951023931953f;
        #pragma unroll 4
        for (int i = 0; i < 32; i++) {
            float t = __shfl_sync(0xffffffffu, ct, i);
            float s0, c0, s1, c1;
            fsincos(f0 * t, s0, c0);
            fsincos(f1 * t, s1, c1);
            STS32(rowBase + i * SA_STRIDE + 128 + lane * 4, packh2(s0, s1));
            STS32(rowBase + i * SA_STRIDE + 256 + lane * 4, packh2(c0, c1));
        }

        #pragma unroll 4
        for (int i = 0; i < 32; i++) {
            float xcx = __shfl_sync(0xffffffffu, cx, i);
            float xcy = __shfl_sync(0xffffffffu, cy, i);
            if (lane < 12) {
                uint32_t w = 0;
                if (lane == 0)      w = packh2(xcx, xcy);
                else if (lane == 1) w = packh2(1.f, 0.f);
                STS32(rowBase + i * SA_STRIDE + 384 + lane * 4, w);
            }
        }
    }
    __syncthreads();   // sb2/sb3 ready

    // ldmatrix A addresses for this warp's two m16 halves
    const uint32_t aAddr0 = sb + SM_A + (uint32_t)(warp * 32 + (lane & 15)) * SA_STRIDE + (lane >> 4) * 16;
    const uint32_t aAddr1 = aAddr0 + 16 * SA_STRIDE;
    // epilogue STS base: row warp*32 + h*16 + (lane>>2), col word (lane&3)
    const uint32_t eAddr0 = sb + SM_A + (uint32_t)(warp * 32 + (lane >> 2)) * SA_STRIDE + (lane & 3) * 4;

    float d[2][16][4];

    // ================= layer 1 (A from smem) =================
    {
        const uint4* wf = g_wfrag4 + WF_L1 + lane;
        uint32_t A0[4], A1[4];
        ldsm4(A0, aAddr0);
        ldsm4(A1, aAddr1);
        mma2_g4_z(d, A0, A1, wf, 0);
        mma2_g4_z(d, A0, A1, wf, 4);
        #pragma unroll 1
        for (int kt = 1; kt < L1_KT; kt++) {
            ldsm4(A0, aAddr0 + kt * 32);
            ldsm4(A1, aAddr1 + kt * 32);
            const uint4* p = wf + kt * 256;
            mma2_g4(d, A0, A1, p, 0);
            mma2_g4(d, A0, A1, p, 4);
        }
    }

    // epilogue 1: tanh -> smem (bias folded into W1)
    #pragma unroll
    for (int h = 0; h < 2; h++) {
        uint32_t ea = eAddr0 + h * (16 * SA_STRIDE);
        #pragma unroll
        for (int nt = 0; nt < 16; nt++) {
            STS32(ea + nt * 16,                   tanh_h2(packh2(d[h][nt][0], d[h][nt][1])));
            STS32(ea + nt * 16 + 8 * SA_STRIDE,   tanh_h2(packh2(d[h][nt][2], d[h][nt][3])));
        }
    }
    __syncwarp();

    // ================= layer 2 =================
    {
        const uint4* wf = g_wfrag4 + WF_L2 + lane;
        uint32_t A0[4], A1[4];
        ldsm4(A0, aAddr0);
        ldsm4(A1, aAddr1);
        mma2_g4_z(d, A0, A1, wf, 0);
        mma2_g4_z(d, A0, A1, wf, 4);
        #pragma unroll 1
        for (int kt = 1; kt < L23_KT; kt++) {
            ldsm4(A0, aAddr0 + kt * 32);
            ldsm4(A1, aAddr1 + kt * 32);
            const uint4* p = wf + kt * 256;
            mma2_g4(d, A0, A1, p, 0);
            mma2_g4(d, A0, A1, p, 4);
        }
    }

    // epilogue 2: +b2, tanh -> smem
    #pragma unroll
    for (int h = 0; h < 2; h++) {
        uint32_t ea = eAddr0 + h * (16 * SA_STRIDE);
        #pragma unroll
        for (int nt = 0; nt < 16; nt++) {
            float2 bb = *(float2*)(sb2 + nt * 8 + (lane & 3) * 2);
            STS32(ea + nt * 16,                 tanh_h2(packh2(d[h][nt][0] + bb.x, d[h][nt][1] + bb.y)));
            STS32(ea + nt * 16 + 8 * SA_STRIDE, tanh_h2(packh2(d[h][nt][2] + bb.x, d[h][nt][3] + bb.y)));
        }
    }
    __syncwarp();

    // ================= layer 3 =================
    {
        const uint4* wf = g_wfrag4 + WF_L3 + lane;
        uint32_t A0[4], A1[4];
        ldsm4(A0, aAddr0);
        ldsm4(A1, aAddr1);
        mma2_g4_z(d, A0, A1, wf, 0);
        mma2_g4_z(d, A0, A1, wf, 4);
        #pragma unroll 1
        for (int kt = 1; kt < L23_KT; kt++) {
            ldsm4(A0, aAddr0 + kt * 32);
            ldsm4(A1, aAddr1 + kt * 32);
            const uint4* p = wf + kt * 256;
            mma2_g4(d, A0, A1, p, 0);
            mma2_g4(d, A0, A1, p, 4);
        }
    }

    // epilogue 3: +b3, tanh -> smem
    #pragma unroll
    for (int h = 0; h < 2; h++) {
        uint32_t ea = eAddr0 + h * (16 * SA_STRIDE);
        #pragma unroll
        for (int nt = 0; nt < 16; nt++) {
            float2 bb = *(float2*)(sb3 + nt * 8 + (lane & 3) * 2);
            STS32(ea + nt * 16,                 tanh_h2(packh2(d[h][nt][0] + bb.x, d[h][nt][1] + bb.y)));
            STS32(ea + nt * 16 + 8 * SA_STRIDE, tanh_h2(packh2(d[h][nt][2] + bb.x, d[h][nt][3] + bb.y)));
        }
    }
    __syncwarp();

    // ================= heads as MMA (N=8; W hi+lo, A via ldsm) =================
    {
        float dh[2][4];
        const uint4* hf = g_hfrag + lane;
        {
            uint4 HW = __ldg(hf);
            uint32_t A0[4], A1[4];
            ldsm4(A0, aAddr0);
            ldsm4(A1, aAddr1);
            mma_f16_z(dh[0], A0, HW.x, HW.y);
            mma_f16(dh[0], A0, HW.z, HW.w);
            mma_f16_z(dh[1], A1, HW.x, HW.y);
            mma_f16(dh[1], A1, HW.z, HW.w);
        }
        #pragma unroll 1
        for (int kt = 1; kt < 8; kt++) {
            uint4 HW = __ldg(hf + kt * 32);
            uint32_t A0[4], A1[4];
            ldsm4(A0, aAddr0 + kt * 32);
            ldsm4(A1, aAddr1 + kt * 32);
            mma_f16(dh[0], A0, HW.x, HW.y);
            mma_f16(dh[0], A0, HW.z, HW.w);
            mma_f16(dh[1], A1, HW.x, HW.y);
            mma_f16(dh[1], A1, HW.z, HW.w);
        }
        int c0 = (lane & 3) * 2;
        float hb0 = g_hb[c0], hb1 = g_hb[c0 + 1];
        int rbase = blockIdx.x * PTS + warp * 32 + (lane >> 2);
        #pragma unroll
        for (int h = 0; h < 2; h++) {
            float a0 = dh[h][0] + hb0, a1 = dh[h][1] + hb1;
            float a2 = dh[h][2] + hb0, a3 = dh[h][3] + hb1;
            if (c0 == 6) {   // col 7 = softplus(.) + MIN_STD
                a1 = fmaxf(a1, 0.f) + log1pf(expf(-fabsf(a1))) + 0.01f;
                a3 = fmaxf(a3, 0.f) + log1pf(expf(-fabsf(a3))) + 0.01f;
            }
            int r0 = rbase + h * 16;
            *(float2*)(out + r0 * 8 + c0)       = make_float2(a0, a1);
            *(float2*)(out + (r0 + 8) * 8 + c0) = make_float2(a2, a3);
        }
    }
}

// ---------------- host launch ----------------
extern "C" void kernel_launch(void* const* d_in, const int* in_sizes, int n_in,
                              void* d_out, int out_size) {
    const float* coords   = (const float*)d_in[0];
    const float* z_grid   = (const float*)d_in[1];
    const float* fourierB = (const float*)d_in[2];
    const float* W1   = (const float*)d_in[3];
    const float* b1   = (const float*)d_in[4];
    const float* W2   = (const float*)d_in[5];
    const float* b2   = (const float*)d_in[6];
    const float* W3   = (const float*)d_in[7];
    const float* b3   = (const float*)d_in[8];
    const float* Wvel = (const float*)d_in[9];
    const float* bvel = (const float*)d_in[10];
    const float* Wfh  = (const float*)d_in[11];
    const float* bfh  = (const float*)d_in[12];
    const float* Wph  = (const float*)d_in[13];
    const float* bph  = (const float*)d_in[14];
    const float* Wmu  = (const float*)d_in[15];
    const float* bmu  = (const float*)d_in[16];
    const float* Wstd = (const float*)d_in[17];
    const float* bstd = (const float*)d_in[18];
    float* out = (float*)d_out;

    static bool attr_set = false;
    if (!attr_set) {
        cudaFuncSetAttribute(pinn_main, cudaFuncAttributeMaxDynamicSharedMemorySize, SM_TOTAL);
        attr_set = true;
    }

    prologue_kernel<<<PRO_TOTAL, 256>>>(
        z_grid, W1, b1, W2, W3,
        Wvel, bvel, Wfh, bfh, Wph, bph, Wmu, bmu, Wstd, bstd);
    pinn_main<<<NBLK, TPB, SM_TOTAL>>>(coords, fourierB, b2, b3, out);
}